// round 7
// baseline (speedup 1.0000x reference)
#include <cuda_runtime.h>
#include <math_constants.h>
#include <cstdint>

// Problem: votes (16,6,6,3,3,32,32,4,4); EM routing, 2 iterations.
#define NPOS   576
#define KHW    9
#define OO     32
#define KDIM   288            // KH*KW*I
#define PERPOS (KDIM*512)
#define EPSC   1e-7f
#define INVT1  0.0005f        // 0.01*(1-0.95^1)
#define INVT2  0.00142625f    // 0.01*(1-0.95^3)

#define NT     1024
#define SL     8
#define KSL    (KDIM/SL)      // 36

// smem layout (floats). s_G aliases the pass-A partial buffer (8192 <= 8704).
#define OFF_G     0            // 32*272 = 8704  per-warp crv partials
#define OFF_G2    8704         // 8704           per-warp crv2 partials
#define OFF_R1    17408        // 288
#define OFF_A8    17696        // 288
#define OFF_Q2T   17984        // 528  [aa*33+o]
#define OFF_MQ1T  18512        // 528  [aa*33+o]
#define OFF_BASE  19040        // 32
#define OFF_S1    19072        // 8
#define OFF_AV    19080        // 544  [o*17+aa] pass-A sum R1*V
#define OFF_AV2   19624        // 544  [o*17+aa] pass-A sum R1*V^2
#define OFF_GR    20168        // 512  [w*16+m]  per-warp cr partials
#define OFF_SE    20680        // 64   [round*32+w]
#define SMEM_REQ_BYTES (120*1024)   // force 1 CTA/SM -> 85MB L2-resident working set

extern __shared__ float smem[];

__device__ __forceinline__ uint64_t pk2(float lo, float hi) {
    uint64_t r; asm("mov.b64 %0, {%1, %2};" : "=l"(r) : "f"(lo), "f"(hi)); return r;
}
__device__ __forceinline__ void upk2(uint64_t p, float& lo, float& hi) {
    asm("mov.b64 {%0, %1}, %2;" : "=f"(lo), "=f"(hi) : "l"(p));
}
__device__ __forceinline__ uint64_t mul2(uint64_t a, uint64_t b) {
    uint64_t r; asm("mul.rn.f32x2 %0, %1, %2;" : "=l"(r) : "l"(a), "l"(b)); return r;
}
__device__ __forceinline__ uint64_t add2(uint64_t a, uint64_t b) {
    uint64_t r; asm("add.rn.f32x2 %0, %1, %2;" : "=l"(r) : "l"(a), "l"(b)); return r;
}
__device__ __forceinline__ uint64_t fma2(uint64_t a, uint64_t b, uint64_t c) {
    uint64_t r; asm("fma.rn.f32x2 %0, %1, %2, %3;" : "=l"(r) : "l"(a), "l"(b), "l"(c)); return r;
}

__global__ __launch_bounds__(NT, 1)
void em_routing_kernel(const float* __restrict__ votes,
                       const float* __restrict__ activ,
                       const float* __restrict__ beta_a,
                       const float* __restrict__ beta_u,
                       float* __restrict__ out)
{
    float* s_G    = smem + OFF_G;
    float* s_G2   = smem + OFF_G2;
    float* s_R1   = smem + OFF_R1;
    float* s_a8   = smem + OFF_A8;
    float* s_q2T  = smem + OFF_Q2T;
    float* s_mq1T = smem + OFF_MQ1T;
    float* s_base = smem + OFF_BASE;
    float* s_S1   = smem + OFF_S1;
    float* s_av   = smem + OFF_AV;
    float* s_av2  = smem + OFF_AV2;
    float* s_gr   = smem + OFF_GR;
    float* s_se   = smem + OFF_SE;
    float* s_pA   = s_G;                 // pass-A partials alias (8*1024 floats)

    const int t   = threadIdx.x;         // 0..1023
    const int pos = blockIdx.x;
    const float* __restrict__ V  = votes + (int64_t)pos * PERPOS;
    const float* __restrict__ Ai = activ + pos * KDIM;

    // ---- prologue ----
    if (t < KDIM) {
        float a = Ai[t];
        s_a8[t] = 0.8f * a;
        s_R1[t] = (0.8f * a + 0.2f) * (1.0f / 32.0f);
    }
    __syncthreads();
    if (t < 32) {
        float s = 0.f;
        #pragma unroll
        for (int k = t; k < KDIM; k += 32) s += s_R1[k];
        #pragma unroll
        for (int off = 16; off; off >>= 1) s += __shfl_xor_sync(0xffffffffu, s, off);
        if (t == 0) s_S1[0] = s;
    }

    // ---- Pass A: slice sums of R1*V, R1*V^2 (f32x2) ----
    {
        const int sl = t >> 7;           // 0..7
        const int c0 = (t & 127) * 4;
        const ulonglong2* gv = (const ulonglong2*)(V + (size_t)(sl * KSL) * 512 + c0);
        uint64_t av0 = 0, av1 = 0, av20 = 0, av21 = 0;
        #pragma unroll 6
        for (int k = 0; k < KSL; ++k) {
            ulonglong2 v = gv[k * 128];
            float r = s_R1[sl * KSL + k];
            uint64_t r2  = pk2(r, r);
            uint64_t rv0 = mul2(r2, v.x);
            uint64_t rv1 = mul2(r2, v.y);
            av0  = add2(av0, rv0);
            av1  = add2(av1, rv1);
            av20 = fma2(rv0, v.x, av20);
            av21 = fma2(rv1, v.y, av21);
        }
        ulonglong2 st;
        st.x = av0;  st.y = av1;
        *(ulonglong2*)(s_pA + sl * 1024 + c0) = st;
        st.x = av20; st.y = av21;
        *(ulonglong2*)(s_pA + sl * 1024 + 512 + c0) = st;
    }
    __syncthreads();

    // ---- stats closure: mu1/sigma1 tables, per-o base, stash av/av2 ----
    if (t < 512) {
        float av = 0.f, av2 = 0.f;
        #pragma unroll
        for (int ss = 0; ss < SL; ++ss) {
            av  += s_pA[ss * 1024 + t];
            av2 += s_pA[ss * 1024 + 512 + t];
        }
        const int   o     = t >> 4;
        const int   aa    = t & 15;
        const float S1    = s_S1[0];
        const float invS1 = 1.0f / (S1 + EPSC);
        const float mu1   = av * invS1;
        const float sig1  = fmaf(mu1 * mu1, S1, fmaf(-2.0f * mu1, av, av2)) * invS1;
        const float i2s1  = 0.5f / sig1;           // 1/(2 sigma^2), no eps (ref)
        const float q1    = mu1 * i2s1;
        s_q2T [aa * 33 + o] = i2s1;
        s_mq1T[aa * 33 + o] = -2.0f * q1;
        s_av [o * 17 + aa] = av;
        s_av2[o * 17 + aa] = av2;

        float Co   = mu1 * q1;
        float cc0  = __logf(fmaf(2.0f * CUDART_PI_F, sig1, EPSC));
        float cost = (beta_u[o] - 0.5f * __logf(sig1 + EPSC)) * S1;
        #pragma unroll
        for (int off = 8; off; off >>= 1) {
            Co   += __shfl_xor_sync(0xffffffffu, Co,   off);
            cc0  += __shfl_xor_sync(0xffffffffu, cc0,  off);
            cost += __shfl_xor_sync(0xffffffffu, cost, off);
        }
        if (aa == 0) {
            float arg = INVT1 * (beta_a[o] - cost);
            float aj  = 1.0f / (1.0f + __expf(-arg));
            s_base[o] = __logf(aj + EPSC) - cc0 - Co;
        }
    }
    __syncthreads();   // orders s_pA reads before fused pass overwrites s_G

    // ---- Fused E-step + M-step-2: 32 warps; warp w = (o-half h, base-i ib) ----
    {
        const int w  = t >> 5;
        const int l  = t & 31;
        const int h  = w >> 4;           // o-half
        const int ib = w & 15;           // base input capsule
        const int m  = l & 15;           // o & 15
        const int ah = l >> 4;           // aa-half (8 aa each)
        const int o  = h * 16 + m;

        uint64_t q2p[4], mqp[4];
        #pragma unroll
        for (int p = 0; p < 4; ++p) {
            const int aa0 = ah * 8 + 2 * p;
            q2p[p] = pk2(s_q2T [aa0 * 33 + o], s_q2T [(aa0 + 1) * 33 + o]);
            mqp[p] = pk2(s_mq1T[aa0 * 33 + o], s_mq1T[(aa0 + 1) * 33 + o]);
        }
        const float base = s_base[o];
        float* Gp  = s_G  + w * 272 + m * 17 + ah * 8;
        float* G2p = s_G2 + w * 272 + m * 17 + ah * 8;

        #pragma unroll
        for (int round = 0; round < 2; ++round) {
            const int i = ib + 16 * round;
            uint64_t g0 = 0, g1 = 0, g2 = 0, g3 = 0;
            uint64_t q0 = 0, q1 = 0, q2 = 0, q3 = 0;   // sum ep*v^2
            float gr = 0.f, se = 0.f;

            #pragma unroll 3
            for (int j = 0; j < KHW; ++j) {
                const ulonglong2* pv = (const ulonglong2*)
                    (V + (size_t)(j * 32 + i) * 512 + o * 16 + ah * 8);
                ulonglong2 va = pv[0];   // 4 aa
                ulonglong2 vb = pv[1];   // 4 aa
                uint64_t t2 = 0;
                t2 = fma2(va.x, fma2(va.x, q2p[0], mqp[0]), t2);
                t2 = fma2(va.y, fma2(va.y, q2p[1], mqp[1]), t2);
                t2 = fma2(vb.x, fma2(vb.x, q2p[2], mqp[2]), t2);
                t2 = fma2(vb.y, fma2(vb.y, q2p[3], mqp[3]), t2);
                float tlo, thi;
                upk2(t2, tlo, thi);
                float term = tlo + thi;
                term += __shfl_xor_sync(0xffffffffu, term, 16);  // pair aa-halves
                float e = __expf(base - term);    // un-normalized; fp32-safe range
                se += e;
                float ep = s_a8[j * 32 + i] * e;
                gr += ep;
                uint64_t ep2 = pk2(ep, ep);
                uint64_t rv;
                rv = mul2(ep2, va.x); g0 = add2(g0, rv); q0 = fma2(rv, va.x, q0);
                rv = mul2(ep2, va.y); g1 = add2(g1, rv); q1 = fma2(rv, va.y, q1);
                rv = mul2(ep2, vb.x); g2 = add2(g2, rv); q2 = fma2(rv, vb.x, q2);
                rv = mul2(ep2, vb.y); g3 = add2(g3, rv); q3 = fma2(rv, vb.y, q3);
            }

            // warp sum of se: counts each e twice (two ah lanes) over this o-half
            #pragma unroll
            for (int off = 16; off; off >>= 1)
                se += __shfl_xor_sync(0xffffffffu, se, off);
            if (l == 0) s_se[round * 32 + w] = se;
            __syncthreads();
            // s_i over all 32 o: this warp's half + partner warp (w^16), halve dup
            const float invs =
                1.0f / (0.5f * (s_se[round * 32 + w] + s_se[round * 32 + (w ^ 16)]));

            float lo, hi;
            if (round == 0) {
                upk2(g0, lo, hi); Gp [0] = invs*lo; Gp [1] = invs*hi;
                upk2(g1, lo, hi); Gp [2] = invs*lo; Gp [3] = invs*hi;
                upk2(g2, lo, hi); Gp [4] = invs*lo; Gp [5] = invs*hi;
                upk2(g3, lo, hi); Gp [6] = invs*lo; Gp [7] = invs*hi;
                upk2(q0, lo, hi); G2p[0] = invs*lo; G2p[1] = invs*hi;
                upk2(q1, lo, hi); G2p[2] = invs*lo; G2p[3] = invs*hi;
                upk2(q2, lo, hi); G2p[4] = invs*lo; G2p[5] = invs*hi;
                upk2(q3, lo, hi); G2p[6] = invs*lo; G2p[7] = invs*hi;
                if (ah == 0) s_gr[w * 16 + m] = invs * gr;
            } else {
                upk2(g0, lo, hi); Gp [0] += invs*lo; Gp [1] += invs*hi;
                upk2(g1, lo, hi); Gp [2] += invs*lo; Gp [3] += invs*hi;
                upk2(g2, lo, hi); Gp [4] += invs*lo; Gp [5] += invs*hi;
                upk2(g3, lo, hi); Gp [6] += invs*lo; Gp [7] += invs*hi;
                upk2(q0, lo, hi); G2p[0] += invs*lo; G2p[1] += invs*hi;
                upk2(q1, lo, hi); G2p[2] += invs*lo; G2p[3] += invs*hi;
                upk2(q2, lo, hi); G2p[4] += invs*lo; G2p[5] += invs*hi;
                upk2(q3, lo, hi); G2p[6] += invs*lo; G2p[7] += invs*hi;
                if (ah == 0) s_gr[w * 16 + m] += invs * gr;
            }
        }
    }
    __syncthreads();

    // ---- final closure: combine 16 warp partials + 0.2*(pass-A sums) ----
    if (t < 512) {
        const int o   = t >> 4;
        const int aa  = t & 15;
        const int h   = o >> 4;
        const int m   = o & 15;
        float crv  = 0.2f * s_av [o * 17 + aa];
        float crv2 = 0.2f * s_av2[o * 17 + aa];
        float cr   = 0.2f * s_S1[0];
        #pragma unroll
        for (int wl = 0; wl < 16; ++wl) {
            const int w = h * 16 + wl;
            crv  += s_G [w * 272 + m * 17 + aa];
            crv2 += s_G2[w * 272 + m * 17 + aa];
            cr   += s_gr[w * 16 + m];
        }
        const float invR = 1.0f / (cr + EPSC);
        const float mu2  = crv * invR;
        out[pos * 512 + t] = mu2;                                  // poses

        const float sig2 = fmaf(mu2 * mu2, cr, fmaf(-2.0f * mu2, crv, crv2)) * invR;
        float cost2 = (beta_u[o] - 0.5f * __logf(sig2 + EPSC)) * cr;
        #pragma unroll
        for (int off = 8; off; off >>= 1)
            cost2 += __shfl_xor_sync(0xffffffffu, cost2, off);
        if (aa == 0) {
            float arg = INVT2 * (beta_a[o] - cost2);
            out[NPOS * 512 + pos * OO + o] = 1.0f / (1.0f + __expf(-arg)); // acts
        }
    }
}

extern "C" void kernel_launch(void* const* d_in, const int* in_sizes, int n_in,
                              void* d_out, int out_size) {
    const float* votes  = (const float*)d_in[0];
    const float* activ  = (const float*)d_in[1];
    const float* beta_a = (const float*)d_in[2];
    const float* beta_u = (const float*)d_in[3];

    cudaFuncSetAttribute(em_routing_kernel,
                         cudaFuncAttributeMaxDynamicSharedMemorySize,
                         SMEM_REQ_BYTES);

    em_routing_kernel<<<NPOS, NT, SMEM_REQ_BYTES>>>(
        votes, activ, beta_a, beta_u, (float*)d_out);
}

// round 8
// speedup vs baseline: 1.0358x; 1.0358x over previous
#include <cuda_runtime.h>
#include <math_constants.h>
#include <cstdint>

// Problem: votes (16,6,6,3,3,32,32,4,4); EM routing, 2 iterations.
#define NPOS   576
#define KHW    9
#define OO     32
#define KDIM   288            // KH*KW*I
#define PERPOS (KDIM*512)
#define EPSC   1e-7f
#define INVT1  0.0005f        // 0.01*(1-0.95^1)
#define INVT2  0.00142625f    // 0.01*(1-0.95^3)

#define NT     512
#define SL     4
#define KSL    (KDIM/SL)      // 72

// smem layout (floats); total 11784 floats = 47136 B -> 2 CTAs/SM
#define OFF_G     0            // 16*272 = 4352  per-warp crv partials
#define OFF_G2    4352         // 4352           per-warp crv2 partials
#define OFF_R1    8704         // 288
#define OFF_A8    8992         // 288
#define OFF_Q2T   9280         // 528  [aa*33+o]
#define OFF_MQ1T  9808         // 528  [aa*33+o]
#define OFF_BASE  10336        // 32
#define OFF_S1    10368        // 8
#define OFF_AV    10376        // 544  [o*17+aa]
#define OFF_AV2   10920        // 544  [o*17+aa]
#define OFF_GR    11464        // 256  [w*16+m]
#define OFF_SE    11720        // 64   [r*16+w]
#define SMEM_FLOATS 11784
#define SMEM_BYTES  (SMEM_FLOATS*4)

extern __shared__ float smem[];

__device__ __forceinline__ uint64_t pk2(float lo, float hi) {
    uint64_t r; asm("mov.b64 %0, {%1, %2};" : "=l"(r) : "f"(lo), "f"(hi)); return r;
}
__device__ __forceinline__ void upk2(uint64_t p, float& lo, float& hi) {
    asm("mov.b64 {%0, %1}, %2;" : "=f"(lo), "=f"(hi) : "l"(p));
}
__device__ __forceinline__ uint64_t mul2(uint64_t a, uint64_t b) {
    uint64_t r; asm("mul.rn.f32x2 %0, %1, %2;" : "=l"(r) : "l"(a), "l"(b)); return r;
}
__device__ __forceinline__ uint64_t add2(uint64_t a, uint64_t b) {
    uint64_t r; asm("add.rn.f32x2 %0, %1, %2;" : "=l"(r) : "l"(a), "l"(b)); return r;
}
__device__ __forceinline__ uint64_t fma2(uint64_t a, uint64_t b, uint64_t c) {
    uint64_t r; asm("fma.rn.f32x2 %0, %1, %2, %3;" : "=l"(r) : "l"(a), "l"(b), "l"(c)); return r;
}
__device__ __forceinline__ void bar_pair(int id) {   // 2-warp named barrier
    asm volatile("bar.sync %0, 64;" :: "r"(id) : "memory");
}

__global__ __launch_bounds__(NT, 2)
void em_routing_kernel(const float* __restrict__ votes,
                       const float* __restrict__ activ,
                       const float* __restrict__ beta_a,
                       const float* __restrict__ beta_u,
                       float* __restrict__ out)
{
    float* s_G    = smem + OFF_G;
    float* s_G2   = smem + OFF_G2;
    float* s_R1   = smem + OFF_R1;
    float* s_a8   = smem + OFF_A8;
    float* s_q2T  = smem + OFF_Q2T;
    float* s_mq1T = smem + OFF_MQ1T;
    float* s_base = smem + OFF_BASE;
    float* s_S1   = smem + OFF_S1;
    float* s_av   = smem + OFF_AV;
    float* s_av2  = smem + OFF_AV2;
    float* s_gr   = smem + OFF_GR;
    float* s_se   = smem + OFF_SE;
    float* s_pA   = s_G;                 // pass-A partials alias (4096 <= 8704)

    const int t   = threadIdx.x;         // 0..511
    const int pos = blockIdx.x;
    const float* __restrict__ V  = votes + (int64_t)pos * PERPOS;
    const float* __restrict__ Ai = activ + pos * KDIM;

    // ---- prologue ----
    if (t < KDIM) {
        float a = Ai[t];
        s_a8[t] = 0.8f * a;
        s_R1[t] = (0.8f * a + 0.2f) * (1.0f / 32.0f);
    }
    __syncthreads();
    if (t < 32) {
        float s = 0.f;
        #pragma unroll
        for (int k = t; k < KDIM; k += 32) s += s_R1[k];
        #pragma unroll
        for (int off = 16; off; off >>= 1) s += __shfl_xor_sync(0xffffffffu, s, off);
        if (t == 0) s_S1[0] = s;
    }

    // ---- Pass A: slice sums of R1*V, R1*V^2 (f32x2) ----
    {
        const int sl = t >> 7;           // 0..3
        const int c0 = (t & 127) * 4;
        const ulonglong2* gv = (const ulonglong2*)(V + (size_t)(sl * KSL) * 512 + c0);
        uint64_t av0 = 0, av1 = 0, av20 = 0, av21 = 0;
        #pragma unroll 8
        for (int k = 0; k < KSL; ++k) {
            ulonglong2 v = gv[k * 128];
            float r = s_R1[sl * KSL + k];
            uint64_t r2  = pk2(r, r);
            uint64_t rv0 = mul2(r2, v.x);
            uint64_t rv1 = mul2(r2, v.y);
            av0  = add2(av0, rv0);
            av1  = add2(av1, rv1);
            av20 = fma2(rv0, v.x, av20);
            av21 = fma2(rv1, v.y, av21);
        }
        ulonglong2 st;
        st.x = av0;  st.y = av1;
        *(ulonglong2*)(s_pA + sl * 1024 + c0) = st;
        st.x = av20; st.y = av21;
        *(ulonglong2*)(s_pA + sl * 1024 + 512 + c0) = st;
    }
    __syncthreads();

    // ---- stats closure: mu1/sigma1 tables, per-o base, stash av/av2 ----
    {
        float av = 0.f, av2 = 0.f;
        #pragma unroll
        for (int ss = 0; ss < SL; ++ss) {
            av  += s_pA[ss * 1024 + t];
            av2 += s_pA[ss * 1024 + 512 + t];
        }
        const int   o     = t >> 4;
        const int   aa    = t & 15;
        const float S1    = s_S1[0];
        const float invS1 = 1.0f / (S1 + EPSC);
        const float mu1   = av * invS1;
        const float sig1  = fmaf(mu1 * mu1, S1, fmaf(-2.0f * mu1, av, av2)) * invS1;
        const float i2s1  = 0.5f / sig1;           // 1/(2 sigma^2), no eps (ref)
        const float q1    = mu1 * i2s1;
        s_q2T [aa * 33 + o] = i2s1;
        s_mq1T[aa * 33 + o] = -2.0f * q1;
        s_av [o * 17 + aa] = av;
        s_av2[o * 17 + aa] = av2;

        float Co   = mu1 * q1;
        float cc0  = __logf(fmaf(2.0f * CUDART_PI_F, sig1, EPSC));
        float cost = (beta_u[o] - 0.5f * __logf(sig1 + EPSC)) * S1;
        #pragma unroll
        for (int off = 8; off; off >>= 1) {
            Co   += __shfl_xor_sync(0xffffffffu, Co,   off);
            cc0  += __shfl_xor_sync(0xffffffffu, cc0,  off);
            cost += __shfl_xor_sync(0xffffffffu, cost, off);
        }
        if (aa == 0) {
            float arg = INVT1 * (beta_a[o] - cost);
            float aj  = 1.0f / (1.0f + __expf(-arg));
            s_base[o] = __logf(aj + EPSC) - cc0 - Co;
        }
    }
    __syncthreads();   // orders s_pA reads before fused pass overwrites s_G

    // ---- Fused E-step + M-step-2: 16 warps; warp w = (o-half h, ib) ----
    // i rounds: i = ib + 8*r, r = 0..3. Pair {w, w^8} shares i, splits o.
    {
        const int w  = t >> 5;
        const int l  = t & 31;
        const int h  = w >> 3;           // o-half
        const int ib = w & 7;            // base input capsule
        const int m  = l & 15;           // o & 15
        const int ah = l >> 4;           // aa-half (8 aa)
        const int o  = h * 16 + m;
        const int barid = ib + 1;        // named barrier id 1..8

        uint64_t q2p[4], mqp[4];
        #pragma unroll
        for (int p = 0; p < 4; ++p) {
            const int aa0 = ah * 8 + 2 * p;
            q2p[p] = pk2(s_q2T [aa0 * 33 + o], s_q2T [(aa0 + 1) * 33 + o]);
            mqp[p] = pk2(s_mq1T[aa0 * 33 + o], s_mq1T[(aa0 + 1) * 33 + o]);
        }
        const float base = s_base[o];
        float* Gp  = s_G  + w * 272 + m * 17 + ah * 8;
        float* G2p = s_G2 + w * 272 + m * 17 + ah * 8;

        #pragma unroll
        for (int r = 0; r < 4; ++r) {
            const int i = ib + 8 * r;
            uint64_t g0 = 0, g1 = 0, g2 = 0, g3 = 0;
            uint64_t q0 = 0, q1 = 0, q2 = 0, q3 = 0;
            float gr = 0.f, se = 0.f;

            #pragma unroll 3
            for (int j = 0; j < KHW; ++j) {
                const ulonglong2* pv = (const ulonglong2*)
                    (V + (size_t)(j * 32 + i) * 512 + o * 16 + ah * 8);
                ulonglong2 va = pv[0];
                ulonglong2 vb = pv[1];
                uint64_t t2 = 0;
                t2 = fma2(va.x, fma2(va.x, q2p[0], mqp[0]), t2);
                t2 = fma2(va.y, fma2(va.y, q2p[1], mqp[1]), t2);
                t2 = fma2(vb.x, fma2(vb.x, q2p[2], mqp[2]), t2);
                t2 = fma2(vb.y, fma2(vb.y, q2p[3], mqp[3]), t2);
                float tlo, thi;
                upk2(t2, tlo, thi);
                float term = tlo + thi;
                term += __shfl_xor_sync(0xffffffffu, term, 16);  // join aa-halves
                float e = __expf(base - term);   // un-normalized; fp32-safe range
                se += e;
                float ep = s_a8[j * 32 + i] * e;
                gr += ep;
                uint64_t ep2 = pk2(ep, ep);
                uint64_t rv;
                rv = mul2(ep2, va.x); g0 = add2(g0, rv); q0 = fma2(rv, va.x, q0);
                rv = mul2(ep2, va.y); g1 = add2(g1, rv); q1 = fma2(rv, va.y, q1);
                rv = mul2(ep2, vb.x); g2 = add2(g2, rv); q2 = fma2(rv, vb.x, q2);
                rv = mul2(ep2, vb.y); g3 = add2(g3, rv); q3 = fma2(rv, vb.y, q3);
            }

            // warp sum of se: each (o,j) e counted twice (ah dup) over this o-half
            #pragma unroll
            for (int off = 16; off; off >>= 1)
                se += __shfl_xor_sync(0xffffffffu, se, off);
            if (l == 0) s_se[r * 16 + w] = se;
            bar_pair(barid);       // only warps {w, w^8} sync — no block barrier
            const float invs =
                1.0f / (0.5f * (s_se[r * 16 + w] + s_se[r * 16 + (w ^ 8)]));

            float lo, hi;
            if (r == 0) {
                upk2(g0, lo, hi); Gp [0] = invs*lo; Gp [1] = invs*hi;
                upk2(g1, lo, hi); Gp [2] = invs*lo; Gp [3] = invs*hi;
                upk2(g2, lo, hi); Gp [4] = invs*lo; Gp [5] = invs*hi;
                upk2(g3, lo, hi); Gp [6] = invs*lo; Gp [7] = invs*hi;
                upk2(q0, lo, hi); G2p[0] = invs*lo; G2p[1] = invs*hi;
                upk2(q1, lo, hi); G2p[2] = invs*lo; G2p[3] = invs*hi;
                upk2(q2, lo, hi); G2p[4] = invs*lo; G2p[5] = invs*hi;
                upk2(q3, lo, hi); G2p[6] = invs*lo; G2p[7] = invs*hi;
                if (ah == 0) s_gr[w * 16 + m] = invs * gr;
            } else {
                upk2(g0, lo, hi); Gp [0] += invs*lo; Gp [1] += invs*hi;
                upk2(g1, lo, hi); Gp [2] += invs*lo; Gp [3] += invs*hi;
                upk2(g2, lo, hi); Gp [4] += invs*lo; Gp [5] += invs*hi;
                upk2(g3, lo, hi); Gp [6] += invs*lo; Gp [7] += invs*hi;
                upk2(q0, lo, hi); G2p[0] += invs*lo; G2p[1] += invs*hi;
                upk2(q1, lo, hi); G2p[2] += invs*lo; G2p[3] += invs*hi;
                upk2(q2, lo, hi); G2p[4] += invs*lo; G2p[5] += invs*hi;
                upk2(q3, lo, hi); G2p[6] += invs*lo; G2p[7] += invs*hi;
                if (ah == 0) s_gr[w * 16 + m] += invs * gr;
            }
        }
    }
    __syncthreads();

    // ---- final closure: combine 8 warp partials per o-half + 0.2*pass-A ----
    {
        const int o   = t >> 4;
        const int aa  = t & 15;
        const int h   = o >> 4;
        const int m   = o & 15;
        float crv  = 0.2f * s_av [o * 17 + aa];
        float crv2 = 0.2f * s_av2[o * 17 + aa];
        float cr   = 0.2f * s_S1[0];
        #pragma unroll
        for (int ib = 0; ib < 8; ++ib) {
            const int w = h * 8 + ib;
            crv  += s_G [w * 272 + m * 17 + aa];
            crv2 += s_G2[w * 272 + m * 17 + aa];
            cr   += s_gr[w * 16 + m];
        }
        const float invR = 1.0f / (cr + EPSC);
        const float mu2  = crv * invR;
        out[pos * 512 + t] = mu2;                                  // poses

        const float sig2 = fmaf(mu2 * mu2, cr, fmaf(-2.0f * mu2, crv, crv2)) * invR;
        float cost2 = (beta_u[o] - 0.5f * __logf(sig2 + EPSC)) * cr;
        #pragma unroll
        for (int off = 8; off; off >>= 1)
            cost2 += __shfl_xor_sync(0xffffffffu, cost2, off);
        if (aa == 0) {
            float arg = INVT2 * (beta_a[o] - cost2);
            out[NPOS * 512 + pos * OO + o] = 1.0f / (1.0f + __expf(-arg)); // acts
        }
    }
}

extern "C" void kernel_launch(void* const* d_in, const int* in_sizes, int n_in,
                              void* d_out, int out_size) {
    const float* votes  = (const float*)d_in[0];
    const float* activ  = (const float*)d_in[1];
    const float* beta_a = (const float*)d_in[2];
    const float* beta_u = (const float*)d_in[3];

    cudaFuncSetAttribute(em_routing_kernel,
                         cudaFuncAttributeMaxDynamicSharedMemorySize,
                         SMEM_BYTES);

    em_routing_kernel<<<NPOS, NT, SMEM_BYTES>>>(
        votes, activ, beta_a, beta_u, (float*)d_out);
}

// round 9
// speedup vs baseline: 1.1157x; 1.0772x over previous
#include <cuda_runtime.h>
#include <math_constants.h>
#include <cstdint>

// Problem: votes (16,6,6,3,3,32,32,4,4); EM routing, 2 iterations.
// Cluster of 2 CTAs per position; CTA q owns input capsules i in [16q, 16q+16).
// Per-CTA V slab = 288KB -> 296 concurrent CTAs * 288KB = 85MB, L2-resident.
#define NPOS   576
#define KHW    9
#define OO     32
#define KDIM   288            // KH*KW*I
#define PERPOS (KDIM*512)
#define EPSC   1e-7f
#define INVT1  0.0005f        // 0.01*(1-0.95^1)
#define INVT2  0.00142625f    // 0.01*(1-0.95^3)

#define NT     512

// smem layout (floats); ~56KB -> 2 CTAs/SM (regs also cap at 2)
#define OFF_G     0            // 16*272 = 4352  per-warp crv partials (pass-A alias)
#define OFF_G2    4352         // 4352           per-warp crv2 partials
#define OFF_R1    8704         // 288
#define OFF_A8    8992         // 288
#define OFF_Q2T   9280         // 528  [aa*33+o]
#define OFF_MQ1T  9808         // 528  [aa*33+o]
#define OFF_BASE  10336        // 32
#define OFF_S1    10368        // 8
#define OFF_AV    10376        // 544  [o*17+aa] own-half sum R1*V
#define OFF_AV2   10920        // 544
#define OFF_AVF   11464        // 544  combined (both halves)
#define OFF_AV2F  12008        // 544
#define OFF_GR    12552        // 256  [w*16+m]
#define OFF_SE    12808        // 32   [r*16+w]
#define OFF_FA    12840        // 544  local e-part crv
#define OFF_FB    13384        // 544  local e-part crv2
#define OFF_FC    13928        // 32   local e-part cr (per o)
#define SMEM_FLOATS 13960
#define SMEM_BYTES  (SMEM_FLOATS*4)

extern __shared__ float smem[];

__device__ __forceinline__ uint64_t pk2(float lo, float hi) {
    uint64_t r; asm("mov.b64 %0, {%1, %2};" : "=l"(r) : "f"(lo), "f"(hi)); return r;
}
__device__ __forceinline__ void upk2(uint64_t p, float& lo, float& hi) {
    asm("mov.b64 {%0, %1}, %2;" : "=f"(lo), "=f"(hi) : "l"(p));
}
__device__ __forceinline__ uint64_t mul2(uint64_t a, uint64_t b) {
    uint64_t r; asm("mul.rn.f32x2 %0, %1, %2;" : "=l"(r) : "l"(a), "l"(b)); return r;
}
__device__ __forceinline__ uint64_t add2(uint64_t a, uint64_t b) {
    uint64_t r; asm("add.rn.f32x2 %0, %1, %2;" : "=l"(r) : "l"(a), "l"(b)); return r;
}
__device__ __forceinline__ uint64_t fma2(uint64_t a, uint64_t b, uint64_t c) {
    uint64_t r; asm("fma.rn.f32x2 %0, %1, %2, %3;" : "=l"(r) : "l"(a), "l"(b), "l"(c)); return r;
}
__device__ __forceinline__ void bar_pair(int id) {   // 2-warp named barrier
    asm volatile("bar.sync %0, 64;" :: "r"(id) : "memory");
}
__device__ __forceinline__ uint32_t smem_u32(const void* p) {
    uint32_t r;
    asm("{ .reg .u64 t; cvta.to.shared.u64 t, %1; cvt.u32.u64 %0, t; }"
        : "=r"(r) : "l"(p));
    return r;
}
__device__ __forceinline__ uint32_t mapa_rank(uint32_t addr, uint32_t rank) {
    uint32_t r;
    asm("mapa.shared::cluster.u32 %0, %1, %2;" : "=r"(r) : "r"(addr), "r"(rank));
    return r;
}
__device__ __forceinline__ float ld_dsm(uint32_t addr) {
    float v;
    asm volatile("ld.shared::cluster.f32 %0, [%1];" : "=f"(v) : "r"(addr));
    return v;
}
__device__ __forceinline__ void cluster_sync() {
    asm volatile("barrier.cluster.arrive.aligned;" ::: "memory");
    asm volatile("barrier.cluster.wait.aligned;"   ::: "memory");
}
__device__ __forceinline__ uint32_t ctarank() {
    uint32_t r;
    asm("mov.u32 %0, %%cluster_ctarank;" : "=r"(r));
    return r;
}

__global__ __launch_bounds__(NT, 2) __cluster_dims__(2, 1, 1)
void em_routing_kernel(const float* __restrict__ votes,
                       const float* __restrict__ activ,
                       const float* __restrict__ beta_a,
                       const float* __restrict__ beta_u,
                       float* __restrict__ out)
{
    float* s_G    = smem + OFF_G;
    float* s_G2   = smem + OFF_G2;
    float* s_R1   = smem + OFF_R1;
    float* s_a8   = smem + OFF_A8;
    float* s_q2T  = smem + OFF_Q2T;
    float* s_mq1T = smem + OFF_MQ1T;
    float* s_base = smem + OFF_BASE;
    float* s_S1   = smem + OFF_S1;
    float* s_av   = smem + OFF_AV;
    float* s_av2  = smem + OFF_AV2;
    float* s_avF  = smem + OFF_AVF;
    float* s_av2F = smem + OFF_AV2F;
    float* s_gr   = smem + OFF_GR;
    float* s_se   = smem + OFF_SE;
    float* s_fA   = smem + OFF_FA;
    float* s_fB   = smem + OFF_FB;
    float* s_fC   = smem + OFF_FC;
    float* s_pA   = s_G;               // pass-A slice partials alias (4096 <= 4352+)

    const int t    = threadIdx.x;      // 0..511
    const int q    = (int)ctarank();   // 0 or 1
    const int peer = q ^ 1;
    const int q16  = 16 * q;
    const int pos  = blockIdx.x >> 1;
    const float* __restrict__ V  = votes + (int64_t)pos * PERPOS;
    const float* __restrict__ Ai = activ + pos * KDIM;

    // ---- prologue: full R1/a8 tables, local S1 (global sum, no comm) ----
    if (t < KDIM) {
        float a = Ai[t];
        s_a8[t] = 0.8f * a;
        s_R1[t] = (0.8f * a + 0.2f) * (1.0f / 32.0f);
    }
    __syncthreads();
    if (t < 32) {
        float s = 0.f;
        #pragma unroll
        for (int k = t; k < KDIM; k += 32) s += s_R1[k];
        #pragma unroll
        for (int off = 16; off; off >>= 1) s += __shfl_xor_sync(0xffffffffu, s, off);
        if (t == 0) s_S1[0] = s;
    }

    // ---- Pass A over OWN half: slice sl handles il in [4sl,4sl+4), all j ----
    {
        const int sl = t >> 7;           // 0..3
        const int c0 = (t & 127) * 4;
        const ulonglong2* gv =
            (const ulonglong2*)(V + (size_t)(q16 + 4 * sl) * 512 + c0);
        const float* r1 = s_R1 + q16 + 4 * sl;
        uint64_t av0 = 0, av1 = 0, av20 = 0, av21 = 0;
        #pragma unroll
        for (int j = 0; j < KHW; ++j) {
            #pragma unroll
            for (int ilr = 0; ilr < 4; ++ilr) {
                ulonglong2 v = gv[(j * 32 + ilr) * 128];
                float r = r1[j * 32 + ilr];
                uint64_t r2  = pk2(r, r);
                uint64_t rv0 = mul2(r2, v.x);
                uint64_t rv1 = mul2(r2, v.y);
                av0  = add2(av0, rv0);
                av1  = add2(av1, rv1);
                av20 = fma2(rv0, v.x, av20);
                av21 = fma2(rv1, v.y, av21);
            }
        }
        ulonglong2 st;
        st.x = av0;  st.y = av1;
        *(ulonglong2*)(s_pA + sl * 1024 + c0) = st;
        st.x = av20; st.y = av21;
        *(ulonglong2*)(s_pA + sl * 1024 + 512 + c0) = st;
    }
    __syncthreads();

    // ---- local combine -> per-(o,aa) own-half partials ----
    {
        float av = 0.f, av2 = 0.f;
        #pragma unroll
        for (int ss = 0; ss < 4; ++ss) {
            av  += s_pA[ss * 1024 + t];
            av2 += s_pA[ss * 1024 + 512 + t];
        }
        const int idx = (t >> 4) * 17 + (t & 15);
        s_av [idx] = av;
        s_av2[idx] = av2;
    }
    cluster_sync();   // #1: partials visible to peer

    // ---- stats: combine halves (redundant in both CTAs), build tables ----
    {
        const int o   = t >> 4;
        const int aa  = t & 15;
        const int idx = o * 17 + aa;
        const float av  = s_av [idx] + ld_dsm(mapa_rank(smem_u32(s_av)  + idx * 4, peer));
        const float av2 = s_av2[idx] + ld_dsm(mapa_rank(smem_u32(s_av2) + idx * 4, peer));
        s_avF [idx] = av;
        s_av2F[idx] = av2;
        const float S1    = s_S1[0];
        const float invS1 = 1.0f / (S1 + EPSC);
        const float mu1   = av * invS1;
        const float sig1  = fmaf(mu1 * mu1, S1, fmaf(-2.0f * mu1, av, av2)) * invS1;
        const float i2s1  = 0.5f / sig1;           // 1/(2 sigma^2), no eps (ref)
        const float q1    = mu1 * i2s1;
        s_q2T [aa * 33 + o] = i2s1;
        s_mq1T[aa * 33 + o] = -2.0f * q1;

        float Co   = mu1 * q1;
        float cc0  = __logf(fmaf(2.0f * CUDART_PI_F, sig1, EPSC));
        float cost = (beta_u[o] - 0.5f * __logf(sig1 + EPSC)) * S1;
        #pragma unroll
        for (int off = 8; off; off >>= 1) {
            Co   += __shfl_xor_sync(0xffffffffu, Co,   off);
            cc0  += __shfl_xor_sync(0xffffffffu, cc0,  off);
            cost += __shfl_xor_sync(0xffffffffu, cost, off);
        }
        if (aa == 0) {
            float arg = INVT1 * (beta_a[o] - cost);
            float aj  = 1.0f / (1.0f + __expf(-arg));
            s_base[o] = __logf(aj + EPSC) - cc0 - Co;
        }
    }
    __syncthreads();   // tables ready; also orders s_pA reads before s_G reuse

    // ---- Fused E-step + M-step-2 over OWN 16 i's (from L2) ----
    // 16 warps; warp w = (o-half h = w>>3, ib = w&7); rounds r=0..1, i = q16+ib+8r.
    {
        const int w  = t >> 5;
        const int l  = t & 31;
        const int h  = w >> 3;
        const int ib = w & 7;
        const int m  = l & 15;
        const int ah = l >> 4;
        const int o  = h * 16 + m;
        const int barid = ib + 1;

        uint64_t q2p[4], mqp[4];
        #pragma unroll
        for (int p = 0; p < 4; ++p) {
            const int aa0 = ah * 8 + 2 * p;
            q2p[p] = pk2(s_q2T [aa0 * 33 + o], s_q2T [(aa0 + 1) * 33 + o]);
            mqp[p] = pk2(s_mq1T[aa0 * 33 + o], s_mq1T[(aa0 + 1) * 33 + o]);
        }
        const float base = s_base[o];
        float* Gp  = s_G  + w * 272 + m * 17 + ah * 8;
        float* G2p = s_G2 + w * 272 + m * 17 + ah * 8;

        #pragma unroll
        for (int r = 0; r < 2; ++r) {
            const int i = q16 + ib + 8 * r;
            uint64_t g0 = 0, g1 = 0, g2 = 0, g3 = 0;
            uint64_t e0 = 0, e1 = 0, e2 = 0, e3 = 0;
            float gr = 0.f, se = 0.f;

            #pragma unroll 3
            for (int j = 0; j < KHW; ++j) {
                const ulonglong2* pv = (const ulonglong2*)
                    (V + (size_t)(j * 32 + i) * 512 + o * 16 + ah * 8);
                ulonglong2 va = pv[0];
                ulonglong2 vb = pv[1];
                uint64_t t2 = 0;
                t2 = fma2(va.x, fma2(va.x, q2p[0], mqp[0]), t2);
                t2 = fma2(va.y, fma2(va.y, q2p[1], mqp[1]), t2);
                t2 = fma2(vb.x, fma2(vb.x, q2p[2], mqp[2]), t2);
                t2 = fma2(vb.y, fma2(vb.y, q2p[3], mqp[3]), t2);
                float tlo, thi;
                upk2(t2, tlo, thi);
                float term = tlo + thi;
                term += __shfl_xor_sync(0xffffffffu, term, 16);  // join aa-halves
                float e = __expf(base - term);   // un-normalized; fp32-safe range
                se += e;
                float ep = s_a8[j * 32 + i] * e;
                gr += ep;
                uint64_t ep2 = pk2(ep, ep);
                uint64_t rv;
                rv = mul2(ep2, va.x); g0 = add2(g0, rv); e0 = fma2(rv, va.x, e0);
                rv = mul2(ep2, va.y); g1 = add2(g1, rv); e1 = fma2(rv, va.y, e1);
                rv = mul2(ep2, vb.x); g2 = add2(g2, rv); e2 = fma2(rv, vb.x, e2);
                rv = mul2(ep2, vb.y); g3 = add2(g3, rv); e3 = fma2(rv, vb.y, e3);
            }

            // se over warp (each e counted twice by the two ah lanes)
            #pragma unroll
            for (int off = 16; off; off >>= 1)
                se += __shfl_xor_sync(0xffffffffu, se, off);
            if (l == 0) s_se[r * 16 + w] = se;
            bar_pair(barid);       // pair {w, w^8} only
            const float invs =
                1.0f / (0.5f * (s_se[r * 16 + w] + s_se[r * 16 + (w ^ 8)]));

            float lo, hi;
            if (r == 0) {
                upk2(g0, lo, hi); Gp [0] = invs*lo; Gp [1] = invs*hi;
                upk2(g1, lo, hi); Gp [2] = invs*lo; Gp [3] = invs*hi;
                upk2(g2, lo, hi); Gp [4] = invs*lo; Gp [5] = invs*hi;
                upk2(g3, lo, hi); Gp [6] = invs*lo; Gp [7] = invs*hi;
                upk2(e0, lo, hi); G2p[0] = invs*lo; G2p[1] = invs*hi;
                upk2(e1, lo, hi); G2p[2] = invs*lo; G2p[3] = invs*hi;
                upk2(e2, lo, hi); G2p[4] = invs*lo; G2p[5] = invs*hi;
                upk2(e3, lo, hi); G2p[6] = invs*lo; G2p[7] = invs*hi;
                if (ah == 0) s_gr[w * 16 + m] = invs * gr;
            } else {
                upk2(g0, lo, hi); Gp [0] += invs*lo; Gp [1] += invs*hi;
                upk2(g1, lo, hi); Gp [2] += invs*lo; Gp [3] += invs*hi;
                upk2(g2, lo, hi); Gp [4] += invs*lo; Gp [5] += invs*hi;
                upk2(g3, lo, hi); Gp [6] += invs*lo; Gp [7] += invs*hi;
                upk2(e0, lo, hi); G2p[0] += invs*lo; G2p[1] += invs*hi;
                upk2(e1, lo, hi); G2p[2] += invs*lo; G2p[3] += invs*hi;
                upk2(e2, lo, hi); G2p[4] += invs*lo; G2p[5] += invs*hi;
                upk2(e3, lo, hi); G2p[6] += invs*lo; G2p[7] += invs*hi;
                if (ah == 0) s_gr[w * 16 + m] += invs * gr;
            }
        }
    }
    __syncthreads();

    // ---- local e-part combine per (o,aa) over this CTA's 8 warps ----
    {
        const int o   = t >> 4;
        const int aa  = t & 15;
        const int h   = o >> 4;
        const int m   = o & 15;
        const int idx = o * 17 + aa;
        float crv = 0.f, crv2 = 0.f, cr = 0.f;
        #pragma unroll
        for (int ib = 0; ib < 8; ++ib) {
            const int w = h * 8 + ib;
            crv  += s_G [w * 272 + m * 17 + aa];
            crv2 += s_G2[w * 272 + m * 17 + aa];
            cr   += s_gr[w * 16 + m];
        }
        s_fA[idx] = crv;
        s_fB[idx] = crv2;
        if (aa == 0) s_fC[o] = cr;
    }
    cluster_sync();   // #2: e-partials visible to peer

    // ---- output: CTA q writes o in [16q, 16q+16) ----
    if (t < 256) {
        const int o   = q16 + (t >> 4);
        const int aa  = t & 15;
        const int idx = o * 17 + aa;
        float crv  = s_fA[idx] + ld_dsm(mapa_rank(smem_u32(s_fA) + idx * 4, peer))
                   + 0.2f * s_avF[idx];
        float crv2 = s_fB[idx] + ld_dsm(mapa_rank(smem_u32(s_fB) + idx * 4, peer))
                   + 0.2f * s_av2F[idx];
        float cr   = s_fC[o] + ld_dsm(mapa_rank(smem_u32(s_fC) + o * 4, peer))
                   + 0.2f * s_S1[0];

        const float invR = 1.0f / (cr + EPSC);
        const float mu2  = crv * invR;
        out[pos * 512 + o * 16 + aa] = mu2;                        // poses

        const float sig2 = fmaf(mu2 * mu2, cr, fmaf(-2.0f * mu2, crv, crv2)) * invR;
        float cost2 = (beta_u[o] - 0.5f * __logf(sig2 + EPSC)) * cr;
        #pragma unroll
        for (int off = 8; off; off >>= 1)
            cost2 += __shfl_xor_sync(0xffffffffu, cost2, off);
        if (aa == 0) {
            float arg = INVT2 * (beta_a[o] - cost2);
            out[NPOS * 512 + pos * OO + o] = 1.0f / (1.0f + __expf(-arg)); // acts
        }
    }

    cluster_sync();   // #3: peer may still be reading our smem
}

extern "C" void kernel_launch(void* const* d_in, const int* in_sizes, int n_in,
                              void* d_out, int out_size) {
    const float* votes  = (const float*)d_in[0];
    const float* activ  = (const float*)d_in[1];
    const float* beta_a = (const float*)d_in[2];
    const float* beta_u = (const float*)d_in[3];

    cudaFuncSetAttribute(em_routing_kernel,
                         cudaFuncAttributeMaxDynamicSharedMemorySize,
                         SMEM_BYTES);

    em_routing_kernel<<<NPOS * 2, NT, SMEM_BYTES>>>(
        votes, activ, beta_a, beta_u, (float*)d_out);
}